// round 17
// baseline (speedup 1.0000x reference)
#include <cuda_runtime.h>
#include <math.h>

#define NB   64
#define NN   1024
#define FIN  14
#define NH   128
#define NTOT (NB*NN)        /* 65536 */
#define NE   (NTOT*8)       /* 524288 */
#define EPG  8192           /* edges per graph (exact: NN*DEG) */
#define KP1  820
#define KP2  656

/* ---------------- scratch (device globals; no allocs allowed) ---------------- */
__device__ __align__(16) int      g_rows[NTOT + 16];
__device__ int                    g_esrc[NE];
__device__ __align__(16) float    g_h1[NTOT * NH];
__device__ __align__(16) float    g_agg2[NTOT * NH];
__device__ __align__(16) float    g_h2[NTOT * NH];
__device__ float                  g_logit1[NTOT];
__device__ float                  g_logit2[NTOT];
__device__ float                  g_scale1[NTOT];
__device__ int                    g_kept1[NTOT];
__device__ int                    g_rank1[NTOT];

/* HW tanh: tanh.approx.f32 (MUFU.TANH) — matches the reference bit-for-bit. */
__device__ __forceinline__ float tanh_hw(float x) {
    float y;
    asm("tanh.approx.f32 %0, %1;" : "=f"(y) : "f"(x));
    return y;
}

/* TF32 operand rounding (RNA) — cuBLAS convention for f32 tensor-core GEMM */
__device__ __forceinline__ unsigned tf32u(float a) {
    unsigned r;
    asm("cvt.rna.tf32.f32 %0, %1;" : "=r"(r) : "f"(a));
    return r;
}

/* ---- fused per-graph CSR build: smem hist + scan + scatter (1 kernel) ---- */
__global__ void __launch_bounds__(1024)
k_csr(const int* __restrict__ src, const int* __restrict__ dst) {
    __shared__ int cnt[NN];
    __shared__ int pref[NN];

    int g = blockIdx.x, t = threadIdx.x;
    int ebase = g * EPG;
    int vbase = g * NN;

    cnt[t] = 0;
    __syncthreads();

    int dl[8], sl[8];
#pragma unroll
    for (int q = 0; q < 8; q++) {
        int e = ebase + q * 1024 + t;
        dl[q] = dst[e] - vbase;
        sl[q] = src[e];
        atomicAdd(&cnt[dl[q]], 1);
    }
    __syncthreads();

    int v = cnt[t];
    pref[t] = v;
    __syncthreads();
    for (int off = 1; off < 1024; off <<= 1) {
        int x = 0;
        if (t >= off) x = pref[t - off];
        __syncthreads();
        if (t >= off) pref[t] += x;
        __syncthreads();
    }
    int excl = pref[t] - v;
    g_rows[vbase + t] = ebase + excl;
    cnt[t] = excl;
    __syncthreads();

#pragma unroll
    for (int q = 0; q < 8; q++) {
        int p = atomicAdd(&cnt[dl[q]], 1);
        g_esrc[ebase + p] = sl[q];
    }
    if (g == NB - 1 && t == 0) g_rows[NTOT] = NE;
}

/* ---- conv1: grid-stride, warp per node, MLP-8 prefetch gather, fp32 ---- */
#define C1GRID 1184
__global__ void __launch_bounds__(256)
k_conv1(const float* __restrict__ x,
        const float* __restrict__ W1rel, const float* __restrict__ b1,
        const float* __restrict__ W1root, const float* __restrict__ p1w) {
    __shared__ float sWrel[NH * FIN];
    __shared__ float sWroot[NH * FIN];
    __shared__ float sb[NH];
    __shared__ float spw[NH];
    __shared__ float sAgg[8][FIN];
    __shared__ float sXv[8][FIN];

    int tid = threadIdx.x;
    for (int i = tid; i < NH * FIN; i += 256) {
        sWrel[i]  = W1rel[i];
        sWroot[i] = W1root[i];
    }
    if (tid < NH) { sb[tid] = b1[tid]; spw[tid] = p1w[tid]; }
    __syncthreads();

    int w    = tid >> 5;
    int lane = tid & 31;

    for (int blk = blockIdx.x; blk < NTOT / 8; blk += C1GRID) {
        int v = blk * 8 + w;
        int rs = g_rows[v], re = g_rows[v + 1];
        if (lane < FIN) {
            float a[4] = {0.f, 0.f, 0.f, 0.f};
            for (int i = rs; i < re; i += 8) {
                int n = re - i;
                int s[8];
#pragma unroll
                for (int q = 0; q < 8; q++) s[q] = (q < n) ? g_esrc[i + q] : 0;
#pragma unroll
                for (int q = 0; q < 8; q++)
                    if (q < n) a[q & 3] += x[s[q] * FIN + lane];
            }
            sAgg[w][lane] = (a[0] + a[1]) + (a[2] + a[3]);
            sXv[w][lane]  = x[v * FIN + lane];
        }
        __syncwarp();

        float lp = 0.f;
        float hj[4];
#pragma unroll
        for (int jj = 0; jj < 4; jj++) {
            int j = lane * 4 + jj;
            float acc = sb[j];
#pragma unroll
            for (int k = 0; k < FIN; k++)
                acc += sAgg[w][k] * sWrel[j * FIN + k] + sXv[w][k] * sWroot[j * FIN + k];
            acc = fmaxf(acc, 0.f);
            hj[jj] = acc;
            lp += acc * spw[j];
        }
        *(float4*)&g_h1[v * NH + lane * 4] = make_float4(hj[0], hj[1], hj[2], hj[3]);
#pragma unroll
        for (int o = 16; o > 0; o >>= 1) lp += __shfl_xor_sync(0xffffffffu, lp, o);
        if (lane == 0) g_logit1[v] = lp;
        __syncwarp();
    }
}

/* ------- per-graph top-K + FUSED readout (semantics from R12) ------- */
__device__ __forceinline__ bool pair_before(float va, int ia, float vb, int ib) {
    return (va > vb) || (va == vb && ia < ib);
}

__global__ void __launch_bounds__(1024)
k_pool_readout(const float* __restrict__ logitArr, const int* __restrict__ valid,
               const int* __restrict__ keyIn, const float* __restrict__ w,
               int* __restrict__ keptOut, float* __restrict__ scaleOut,
               int* __restrict__ rankOut,
               const float* __restrict__ h, float* __restrict__ out,
               float invK, int accumulate, int K) {
    __shared__ float sv[NN];
    __shared__ int   si[NN];
    __shared__ float red[128];
    __shared__ float snorm;
    __shared__ float ksc[NN];
    __shared__ int   kkp[NN];
    __shared__ float rsum[8][128];
    __shared__ float rmax[8][128];

    int t = threadIdx.x, g = blockIdx.x;

    if (t < 128) { float w0 = w[t]; red[t] = w0 * w0; }
    __syncthreads();
    if (t < 64) red[t] += red[t + 64];
    __syncthreads();
    if (t < 32) {
        float s = red[t] + red[t + 32];
#pragma unroll
        for (int o = 16; o > 0; o >>= 1) s += __shfl_xor_sync(0xffffffffu, s, o);
        if (t == 0) snorm = __fsqrt_rn(s);
    }
    __syncthreads();

    int orig = g * NN + t;
    float scv = -3.0f;
    int   key;
    if (valid == nullptr || valid[orig]) {
        scv = tanh_hw(__fdiv_rn(logitArr[orig], snorm));
        key = keyIn ? keyIn[orig] : t;
    } else {
        key = 500000 + t;
    }
    sv[t] = scv;
    si[t] = key * 2048 + t;
    __syncthreads();

    for (int k = 2; k <= NN; k <<= 1) {
        for (int j = k >> 1; j > 0; j >>= 1) {
            int ixj = t ^ j;
            if (ixj > t) {
                float va = sv[t], vb = sv[ixj];
                int   ia = si[t], ib = si[ixj];
                bool up = ((t & k) == 0);
                bool swp = up ? pair_before(vb, ib, va, ia)
                              : pair_before(va, ia, vb, ib);
                if (swp) { sv[t] = vb; si[t] = ib; sv[ixj] = va; si[ixj] = ia; }
            }
            __syncthreads();
        }
    }

    int slot = si[t] & 2047;
    int kp   = (t < K) ? 1 : 0;
    float sc = kp ? sv[t] : 0.f;
    kkp[slot] = kp;
    ksc[slot] = sc;
    if (keptOut)  keptOut[g * NN + slot]  = kp;
    if (scaleOut) scaleOut[g * NN + slot] = sc;
    if (rankOut)  rankOut[g * NN + slot]  = t;
    __syncthreads();

    int sub = t >> 7;
    int j   = t & 127;
    float sum = 0.f, mx = -INFINITY;
    int v0 = sub * 128;
#pragma unroll 4
    for (int v = v0; v < v0 + 128; v++) {
        if (kkp[v]) {
            float hv = h[(g * NN + v) * NH + j] * ksc[v];
            sum += hv;
            mx = fmaxf(mx, hv);
        }
    }
    rsum[sub][j] = sum;
    rmax[sub][j] = mx;
    __syncthreads();

    if (t < 128) {
        float s = 0.f, m = -INFINITY;
#pragma unroll
        for (int i = 0; i < 8; i++) {
            s += rsum[i][t];
            m = fmaxf(m, rmax[i][t]);
        }
        float o0 = s * invK;
        if (accumulate) {
            out[g * 256 + t]       += o0;
            out[g * 256 + 128 + t] += m;
        } else {
            out[g * 256 + t]       = o0;
            out[g * 256 + 128 + t] = m;
        }
    }
}

/* ------ conv2 aggregation gather: MLP-8 prefetch (idx, scale, rows) ------ */
__global__ void __launch_bounds__(256)
k_gather2() {
    int tid  = threadIdx.x;
    int w    = tid >> 5;
    int lane = tid & 31;
    int v    = blockIdx.x * 8 + w;
    if (!g_kept1[v]) return;
    int rs = g_rows[v], re = g_rows[v + 1];
    int l4 = lane * 4;
    float4 a0 = make_float4(0.f, 0.f, 0.f, 0.f);
    float4 a1 = make_float4(0.f, 0.f, 0.f, 0.f);
    float4 a2 = make_float4(0.f, 0.f, 0.f, 0.f);
    float4 a3 = make_float4(0.f, 0.f, 0.f, 0.f);

    for (int i = rs; i < re; i += 8) {
        int n = re - i;
        int   s[8];
        float c[8];
#pragma unroll
        for (int q = 0; q < 8; q++) s[q] = (q < n) ? g_esrc[i + q] : 0;
#pragma unroll
        for (int q = 0; q < 8; q++) c[q] = (q < n) ? g_scale1[s[q]] : 0.f;
#pragma unroll
        for (int q = 0; q < 8; q++) {
            if (c[q] != 0.f) {
                float4 hv = *(const float4*)&g_h1[s[q] * NH + l4];
                float4* a = (q & 2) ? ((q & 1) ? &a3 : &a2)
                                    : ((q & 1) ? &a1 : &a0);
                a->x += hv.x * c[q]; a->y += hv.y * c[q];
                a->z += hv.z * c[q]; a->w += hv.w * c[q];
            }
        }
    }
    a0.x = (a0.x + a1.x) + (a2.x + a3.x);
    a0.y = (a0.y + a1.y) + (a2.y + a3.y);
    a0.z = (a0.z + a1.z) + (a2.z + a3.z);
    a0.w = (a0.w + a1.w) + (a2.w + a3.w);
    *(float4*)&g_agg2[v * NH + l4] = a0;
}

/* ---- conv2 GEMM: TF32 tensor cores (mma.m16n8k8) + fused logit2 ---- */
#define G2M  128
#define G2K  32
#define KSTR 36
__global__ void __launch_bounds__(256, 2)
k_gemm2(const float* __restrict__ W2rel, const float* __restrict__ b2,
        const float* __restrict__ W2root, const float* __restrict__ p2w) {
    __shared__ __align__(16) unsigned As[G2M * KSTR];
    __shared__ __align__(16) unsigned Ws[G2M * KSTR];
    __shared__ float sb2[NH];
    __shared__ float sp2[NH];
    __shared__ float slp[G2M][2];

    int tid  = threadIdx.x;
    int m0   = blockIdx.x * G2M;
    int warp = tid >> 5;
    int lane = tid & 31;
    int gq   = lane >> 2;
    int tg   = lane & 3;
    int wm   = warp >> 1;
    int wn   = warp & 1;
    int rbw  = wm * 32;
    int cbw  = wn * 64;

    if (tid < NH) { sb2[tid] = b2[tid]; sp2[tid] = p2w[tid]; }

    float d[2][8][4];
#pragma unroll
    for (int mt = 0; mt < 2; mt++)
#pragma unroll
        for (int nt = 0; nt < 8; nt++)
#pragma unroll
            for (int q = 0; q < 4; q++) d[mt][nt][q] = 0.f;

    for (int kc = 0; kc < 2 * NH; kc += G2K) {
#pragma unroll
        for (int r = 0; r < 4; r++) {
            int id  = tid + r * 256;
            int row = id >> 3;
            int k4  = id & 7;
            int kk  = kc + k4 * 4;
            int node = m0 + row;
            float4 val;
            if (kk < NH) {
                val = *(const float4*)&g_agg2[node * NH + kk];
            } else {
                float sc = g_kept1[node] ? g_scale1[node] : 0.f;
                float4 hh = *(const float4*)&g_h1[node * NH + (kk - NH)];
                val = make_float4(hh.x * sc, hh.y * sc, hh.z * sc, hh.w * sc);
            }
            unsigned* p = &As[row * KSTR + k4 * 4];
            p[0] = tf32u(val.x); p[1] = tf32u(val.y);
            p[2] = tf32u(val.z); p[3] = tf32u(val.w);
        }
#pragma unroll
        for (int r = 0; r < 4; r++) {
            int id  = tid + r * 256;
            int col = id >> 3;
            int k4  = id & 7;
            int kk  = kc + k4 * 4;
            const float* Wsrc = (kk < NH) ? W2rel : W2root;
            int kw = (kk < NH) ? kk : (kk - NH);
            float4 val = *(const float4*)&Wsrc[col * NH + kw];
            unsigned* p = &Ws[col * KSTR + k4 * 4];
            p[0] = tf32u(val.x); p[1] = tf32u(val.y);
            p[2] = tf32u(val.z); p[3] = tf32u(val.w);
        }
        __syncthreads();

#pragma unroll
        for (int ks = 0; ks < 4; ks++) {
            int kb = ks * 8;
            unsigned b0[8], b1[8];
#pragma unroll
            for (int nt = 0; nt < 8; nt++) {
                int cb = cbw + nt * 8;
                b0[nt] = Ws[(cb + gq) * KSTR + kb + tg];
                b1[nt] = Ws[(cb + gq) * KSTR + kb + tg + 4];
            }
#pragma unroll
            for (int mt = 0; mt < 2; mt++) {
                int rb = rbw + mt * 16;
                unsigned a0 = As[(rb + gq) * KSTR + kb + tg];
                unsigned a1 = As[(rb + gq + 8) * KSTR + kb + tg];
                unsigned a2 = As[(rb + gq) * KSTR + kb + tg + 4];
                unsigned a3 = As[(rb + gq + 8) * KSTR + kb + tg + 4];
#pragma unroll
                for (int nt = 0; nt < 8; nt++) {
                    asm volatile(
                        "mma.sync.aligned.m16n8k8.row.col.f32.tf32.tf32.f32 "
                        "{%0,%1,%2,%3}, {%4,%5,%6,%7}, {%8,%9}, {%0,%1,%2,%3};"
                        : "+f"(d[mt][nt][0]), "+f"(d[mt][nt][1]),
                          "+f"(d[mt][nt][2]), "+f"(d[mt][nt][3])
                        : "r"(a0), "r"(a1), "r"(a2), "r"(a3),
                          "r"(b0[nt]), "r"(b1[nt]));
                }
            }
        }
        __syncthreads();
    }

#pragma unroll
    for (int mt = 0; mt < 2; mt++) {
        int r0 = rbw + mt * 16 + gq;
        int r1 = r0 + 8;
        float lp0 = 0.f, lp1 = 0.f;
#pragma unroll
        for (int nt = 0; nt < 8; nt++) {
            int c0 = cbw + nt * 8 + 2 * tg;
            int c1 = c0 + 1;
            float v00 = fmaxf(d[mt][nt][0] + sb2[c0], 0.f);
            float v01 = fmaxf(d[mt][nt][1] + sb2[c1], 0.f);
            float v10 = fmaxf(d[mt][nt][2] + sb2[c0], 0.f);
            float v11 = fmaxf(d[mt][nt][3] + sb2[c1], 0.f);
            *(float2*)&g_h2[(m0 + r0) * NH + c0] = make_float2(v00, v01);
            *(float2*)&g_h2[(m0 + r1) * NH + c0] = make_float2(v10, v11);
            lp0 += v00 * sp2[c0] + v01 * sp2[c1];
            lp1 += v10 * sp2[c0] + v11 * sp2[c1];
        }
        lp0 += __shfl_xor_sync(0xffffffffu, lp0, 1);
        lp0 += __shfl_xor_sync(0xffffffffu, lp0, 2);
        lp1 += __shfl_xor_sync(0xffffffffu, lp1, 1);
        lp1 += __shfl_xor_sync(0xffffffffu, lp1, 2);
        if (tg == 0) {
            slp[r0][wn] = lp0;
            slp[r1][wn] = lp1;
        }
    }
    __syncthreads();

    if (tid < G2M) {
        int node = m0 + tid;
        if (g_kept1[node]) g_logit2[node] = slp[tid][0] + slp[tid][1];
    }
}

/* ---------------- launch ---------------- */
extern "C" void kernel_launch(void* const* d_in, const int* in_sizes, int n_in,
                              void* d_out, int out_size) {
    const float* x      = (const float*)d_in[0];
    const int*   ei     = (const int*)d_in[1];
    /* d_in[2] = batch (unused) */
    const float* W1rel  = (const float*)d_in[3];
    const float* b1     = (const float*)d_in[4];
    const float* W1root = (const float*)d_in[5];
    const float* p1w    = (const float*)d_in[6];
    const float* W2rel  = (const float*)d_in[7];
    const float* b2     = (const float*)d_in[8];
    const float* W2root = (const float*)d_in[9];
    const float* p2w    = (const float*)d_in[10];
    float* out = (float*)d_out;

    const int* src = ei;
    const int* dst = ei + NE;

    float* d_logit1;  cudaGetSymbolAddress((void**)&d_logit1, g_logit1);
    float* d_logit2;  cudaGetSymbolAddress((void**)&d_logit2, g_logit2);
    float* d_scale1;  cudaGetSymbolAddress((void**)&d_scale1, g_scale1);
    int*   d_kept1;   cudaGetSymbolAddress((void**)&d_kept1,  g_kept1);
    int*   d_rank1;   cudaGetSymbolAddress((void**)&d_rank1,  g_rank1);
    float* d_h1;      cudaGetSymbolAddress((void**)&d_h1,     g_h1);
    float* d_h2;      cudaGetSymbolAddress((void**)&d_h2,     g_h2);

    /* CSR build: one fused per-graph kernel */
    k_csr<<<NB, 1024>>>(src, dst);

    /* layer 1 */
    k_conv1<<<C1GRID, 256>>>(x, W1rel, b1, W1root, p1w);
    k_pool_readout<<<NB, 1024>>>(d_logit1, (const int*)nullptr, (const int*)nullptr,
                                 p1w, d_kept1, d_scale1, d_rank1,
                                 d_h1, out, 1.0f / (float)KP1, 0, KP1);

    /* layer 2 */
    k_gather2<<<NTOT / 8, 256>>>();
    k_gemm2<<<NTOT / G2M, 256>>>(W2rel, b2, W2root, p2w);
    k_pool_readout<<<NB, 1024>>>(d_logit2, d_kept1, d_rank1,
                                 p2w, (int*)nullptr, (float*)nullptr, (int*)nullptr,
                                 d_h2, out, 1.0f / (float)KP2, 1, KP2);
}